// round 4
// baseline (speedup 1.0000x reference)
#include <cuda_runtime.h>

#define N_K_STEPS 512
#define N_STATE   128
#define N_INPUT   32
#define HIDDEN    256
#define FAN_IN    161   /* 1 + 128 + 32 */
#define NTHREADS  512

// Tsit5 tableau
__constant__ float c_C[6] = {0.0f, 0.161f, 0.327f, 0.9f, 0.9800255409045097f, 1.0f};
__constant__ float c_A[5][5] = {
  {0.161f, 0.f, 0.f, 0.f, 0.f},
  {-0.008480655492356989f, 0.335480655492357f, 0.f, 0.f, 0.f},
  {2.8971530571054935f, -6.359448489975075f, 4.3622954328695815f, 0.f, 0.f},
  {5.325864828439257f, -11.748883564062828f, 7.4955393428898365f, -0.09249506636175525f, 0.f},
  {5.86145544294642f, -12.92096931784711f, 8.159367898576159f, -0.071584973281401f, -0.028269050394068383f}
};
__constant__ float c_B[6] = {0.09646076681806523f, 0.01f, 0.4798896504144996f,
                             1.379008574103742f, -3.290069515436081f, 2.324710524099774f};

struct SmemLayout {
  float4 zs4[42];           // z padded to 168 floats; [161..167] = 0
  float  hs[HIDDEN];        // hidden activations
  float  partial[4 * 128];  // stage-C partials: [k-slice][output]
  float  ksh[5][128];       // k1..k5
  float  ustg[6][32];       // interpolated u per stage ([0] unused)
  float  tsh[N_K_STEPS];    // ts cached in smem
};

__device__ __forceinline__ float2 ffma2f(float2 a, float2 b, float2 c) {
  union { float2 f; unsigned long long u; } ua, ub, uc;
  ua.f = a; ub.f = b; uc.f = c;
  asm("fma.rn.f32x2 %0, %1, %2, %0;" : "+l"(uc.u) : "l"(ua.u), "l"(ub.u));
  return uc.f;
}

__device__ __forceinline__ float fast_tanh(float x) {
  // tanh(x) = sign(x) * (1 - 2/(1 + e^{2|x|}))  via ex2/rcp approx (~1e-6 abs err)
  float ax = fabsf(x);
  float e;
  asm("ex2.approx.f32 %0, %1;" : "=f"(e) : "f"(ax * 2.885390081777927f)); // 2|x| log2(e)
  float r;
  asm("rcp.approx.f32 %0, %1;" : "=f"(r) : "f"(e + 1.0f));
  float t = fmaf(-2.0f, r, 1.0f);
  return copysignf(t, x);
}

__global__ __launch_bounds__(NTHREADS, 1)
void ode_tsit5_kernel(const float* __restrict__ ts, const float* __restrict__ y0,
                      const float* __restrict__ us, const float* __restrict__ W1,
                      const float* __restrict__ b1, const float* __restrict__ W2,
                      const float* __restrict__ b2, float* __restrict__ out,
                      int n_steps)
{
  __shared__ SmemLayout S;
  const int tid  = threadIdx.x;
  const int lane = tid & 31;
  const int wrp  = tid >> 5;
  const int b    = blockIdx.x;
  const float* usb = us + (size_t)b * N_K_STEPS * N_INPUT;

  // ---- stage-B decomposition: 2 threads per hidden unit, same warp
  const int u    = (wrp << 4) | (lane & 15);   // hidden unit 0..255
  const int half = lane >> 4;                  // 0: z[0:84), 1: z[84:168)
  const int zb   = half * 21;                  // float4 base index into zs4

  // ---- stage-C decomposition: 4 threads per output, 64 k each
  const int o  = tid & 127;                    // output 0..127
  const int sl = tid >> 7;                     // k-slice 0..3

  // ---- one-time: ts -> shared
  for (int i = tid; i < n_steps; i += NTHREADS) S.tsh[i] = ts[i];

  // ---- one-time: W1 half-row -> 21 float4 regs (84 regs)
  float4 w1r[21];
  {
    const float* w1row = W1 + u * FAN_IN;
    #pragma unroll
    for (int j = 0; j < 21; ++j) {
      float v[4];
      #pragma unroll
      for (int c = 0; c < 4; ++c) {
        int f = half * 84 + 4 * j + c;
        v[c] = (f < FAN_IN) ? w1row[f] : 0.0f;
      }
      w1r[j] = make_float4(v[0], v[1], v[2], v[3]);
    }
  }
  // ---- one-time: W2 slice -> 16 float4 regs (64 regs)
  float4 w2r[16];
  {
    const float4* w2v = (const float4*)(W2 + o * HIDDEN + sl * 64);
    #pragma unroll
    for (int j = 0; j < 16; ++j) w2r[j] = w2v[j];
  }
  const float b1t = b1[u];
  const float b2t = b2[o];

  float y_reg = 0.0f;
  if (tid < 128) {
    y_reg = y0[b * N_STATE + tid];
    out[(size_t)b * N_K_STEPS * N_STATE + tid] = y_reg;   // row 0 = y0
  }
  if (tid < 8) ((float*)S.zs4)[160 + tid] = 0.0f;          // pad z[160..167]; [160] overwritten
  __syncthreads();

  float* zsf = (float*)S.zs4;
  const float4* hs4 = (const float4*)S.hs;

  for (int s = 0; s < n_steps - 1; ++s) {
    const float t0 = S.tsh[s];
    const float hstep = S.tsh[s + 1] - t0;

    // ---- step setup: Hermite-interpolated u for stages 1..5
    if (tid < 160) {
      int stg = (tid >> 5) + 1;        // 1..5
      int m   = tid & 31;
      float u0v = usb[s * N_INPUT + m];
      float u1v = usb[(s + 1) * N_INPUT + m];
      float hd1 = u1v - u0v;           // h*d[s+1] == u1-u0 exactly
      float hd0;
      if (s == 0) {
        hd0 = hd1;
      } else {
        float um  = usb[(s - 1) * N_INPUT + m];
        float dtp = t0 - S.tsh[s - 1];
        hd0 = hstep * (u0v - um) / dtp;
      }
      float th = c_C[stg];
      float t2 = th * th, t3 = t2 * th;
      S.ustg[stg][m] = (2.f*t3 - 3.f*t2 + 1.f) * u0v + (t3 - 2.f*t2 + th) * hd0
                     + (-2.f*t3 + 3.f*t2) * u1v + (t3 - t2) * hd1;
    }

    #pragma unroll 1
    for (int st = 0; st < 6; ++st) {
      // ---- (A) assemble z = [t, ytmp, u(theta)]; compute k_{st-1} from partials
      if (st == 0) {
        if (tid < 128)       zsf[1 + tid] = y_reg;
        else if (tid < 160)  zsf[129 + (tid - 128)] = usb[s * N_INPUT + (tid - 128)];
        else if (tid == 160) zsf[0] = t0;
      } else {
        if (tid < 128) {
          float kprev = b2t + S.partial[tid] + S.partial[128 + tid]
                            + S.partial[256 + tid] + S.partial[384 + tid];
          S.ksh[st - 1][tid] = kprev;
          float acc = c_A[st - 1][st - 1] * kprev;
          for (int j = 0; j < st - 1; ++j)
            acc += c_A[st - 1][j] * S.ksh[j][tid];
          zsf[1 + tid] = y_reg + hstep * acc;
        } else if (tid < 160) {
          zsf[129 + (tid - 128)] = S.ustg[st][tid - 128];
        } else if (tid == 160) {
          zsf[0] = t0 + c_C[st] * hstep;
        }
      }
      __syncthreads();

      // ---- (B) hidden half-dot + shfl combine + tanh
      {
        float2 a0 = make_float2(0.f, 0.f), a1 = a0;
        #pragma unroll
        for (int j = 0; j < 21; ++j) {
          float4 zv = S.zs4[zb + j];
          float4 wv = w1r[j];
          a0 = ffma2f(make_float2(wv.x, wv.y), make_float2(zv.x, zv.y), a0);
          a1 = ffma2f(make_float2(wv.z, wv.w), make_float2(zv.z, zv.w), a1);
        }
        float sum = (a0.x + a0.y) + (a1.x + a1.y);
        sum += __shfl_xor_sync(0xffffffffu, sum, 16);
        if (half == 0) S.hs[u] = fast_tanh(sum + b1t);
      }
      __syncthreads();

      // ---- (C) output layer from register-resident W2; h via float4 broadcasts
      {
        float2 c0 = make_float2(0.f, 0.f), c1 = c0, c2 = c0, c3 = c0;
        #pragma unroll
        for (int j = 0; j < 16; j += 2) {
          float4 hv = hs4[sl * 16 + j];
          float4 wv = w2r[j];
          c0 = ffma2f(make_float2(wv.x, wv.y), make_float2(hv.x, hv.y), c0);
          c1 = ffma2f(make_float2(wv.z, wv.w), make_float2(hv.z, hv.w), c1);
          float4 hw = hs4[sl * 16 + j + 1];
          float4 ww = w2r[j + 1];
          c2 = ffma2f(make_float2(ww.x, ww.y), make_float2(hw.x, hw.y), c2);
          c3 = ffma2f(make_float2(ww.z, ww.w), make_float2(hw.z, hw.w), c3);
        }
        S.partial[sl * 128 + o] = (c0.x + c0.y) + (c1.x + c1.y)
                                + (c2.x + c2.y) + (c3.x + c3.y);
      }
      __syncthreads();
    }

    // ---- final Runge-Kutta combine + output write
    if (tid < 128) {
      float k5 = b2t + S.partial[tid] + S.partial[128 + tid]
                     + S.partial[256 + tid] + S.partial[384 + tid];
      float acc = c_B[5] * k5;
      #pragma unroll
      for (int j = 0; j < 5; ++j)
        acc += c_B[j] * S.ksh[j][tid];
      y_reg += hstep * acc;
      out[((size_t)b * N_K_STEPS + (s + 1)) * N_STATE + tid] = y_reg;
    }
    // next iteration's (A)-barrier provides ordering
  }
}

extern "C" void kernel_launch(void* const* d_in, const int* in_sizes, int n_in,
                              void* d_out, int out_size) {
  const float* ts = (const float*)d_in[0];
  const float* y0 = (const float*)d_in[1];
  const float* us = (const float*)d_in[2];
  const float* W1 = (const float*)d_in[3];
  const float* b1 = (const float*)d_in[4];
  const float* W2 = (const float*)d_in[5];
  const float* b2 = (const float*)d_in[6];
  float* out = (float*)d_out;

  const int n_steps = in_sizes[0];             // 512
  const int batch   = in_sizes[1] / N_STATE;   // 64

  ode_tsit5_kernel<<<batch, NTHREADS>>>(ts, y0, us, W1, b1, W2, b2, out, n_steps);
}

// round 6
// speedup vs baseline: 1.9388x; 1.9388x over previous
#include <cuda_runtime.h>

#define N_K_STEPS 512
#define N_STATE   128
#define N_INPUT   32
#define HIDDEN    256
#define FAN_IN    161   /* 1 + 128 + 32 */

// Tsit5 tableau
__constant__ float c_C[6] = {0.0f, 0.161f, 0.327f, 0.9f, 0.9800255409045097f, 1.0f};
__constant__ float c_A[5][5] = {
  {0.161f, 0.f, 0.f, 0.f, 0.f},
  {-0.008480655492356989f, 0.335480655492357f, 0.f, 0.f, 0.f},
  {2.8971530571054935f, -6.359448489975075f, 4.3622954328695815f, 0.f, 0.f},
  {5.325864828439257f, -11.748883564062828f, 7.4955393428898365f, -0.09249506636175525f, 0.f},
  {5.86145544294642f, -12.92096931784711f, 8.159367898576159f, -0.071584973281401f, -0.028269050394068383f}
};
__constant__ float c_B[6] = {0.09646076681806523f, 0.01f, 0.4798896504144996f,
                             1.379008574103742f, -3.290069515436081f, 2.324710524099774f};

struct SmemLayout {
  float4 w2q[64 * 128];     // W2 quads: [k-quad q][output o] = W2[o][4q..4q+3]  (128 KB)
  float4 zs4[41];           // z padded to 164 floats; [161..163] = 0
  float  hs[HIDDEN];        // hidden activations
  float  partial[2 * 128];  // stage-C partials: [half][output]
  float  ksh[5][128];       // k1..k5
  float  ustg[6][32];       // interpolated u per stage ([0] unused)
  float  tsh[N_K_STEPS];    // ts cached in smem
};

__device__ __forceinline__ float2 ffma2f(float2 a, float2 b, float2 c) {
  union { float2 f; unsigned long long u; } ua, ub, uc;
  ua.f = a; ub.f = b; uc.f = c;
  asm("fma.rn.f32x2 %0, %1, %2, %0;" : "+l"(uc.u) : "l"(ua.u), "l"(ub.u));
  return uc.f;
}

__device__ __forceinline__ float fast_tanh(float x) {
  // tanh(x) = sign(x) * (1 - 2/(1 + e^{2|x|}))  via ex2/rcp approx (~1e-6 abs err)
  float ax = fabsf(x);
  float e;
  asm("ex2.approx.f32 %0, %1;" : "=f"(e) : "f"(ax * 2.885390081777927f)); // 2|x|*log2(e)
  float r;
  asm("rcp.approx.f32 %0, %1;" : "=f"(r) : "f"(e + 1.0f));
  float t = fmaf(-2.0f, r, 1.0f);
  return copysignf(t, x);
}

__global__ __launch_bounds__(256, 1)
void ode_tsit5_kernel(const float* __restrict__ ts, const float* __restrict__ y0,
                      const float* __restrict__ us, const float* __restrict__ W1,
                      const float* __restrict__ b1, const float* __restrict__ W2,
                      const float* __restrict__ b2, float* __restrict__ out,
                      int n_steps)
{
  extern __shared__ SmemLayout smem_raw[];
  SmemLayout& S = smem_raw[0];
  const int tid = threadIdx.x;
  const int b   = blockIdx.x;
  const float* usb = us + (size_t)b * N_K_STEPS * N_INPUT;

  // stage-C decomposition: 2 threads per output, 128 k (32 quads) each
  const int o    = tid & 127;
  const int half = tid >> 7;            // 0: k[0:128), 1: k[128:256)
  const int qb   = half * 32;           // k-quad base

  // ---- one-time: W2 -> shared as float4 [k-quad][output]
  for (int idx = tid; idx < 64 * 128; idx += 256) {
    int q = idx >> 7, oo = idx & 127;
    const float* src = W2 + oo * HIDDEN + 4 * q;
    S.w2q[idx] = make_float4(src[0], src[1], src[2], src[3]);
  }
  // ---- one-time: ts -> shared
  for (int i = tid; i < n_steps; i += 256) S.tsh[i] = ts[i];

  // ---- one-time: this thread's W1 row -> 41 float4 regs (164 regs)
  float4 w1r[41];
  {
    const float* w1row = W1 + tid * FAN_IN;
    #pragma unroll
    for (int p = 0; p < 40; ++p)
      w1r[p] = make_float4(w1row[4*p], w1row[4*p+1], w1row[4*p+2], w1row[4*p+3]);
    w1r[40] = make_float4(w1row[160], 0.0f, 0.0f, 0.0f);
  }
  const float b1t = b1[tid];
  const float b2t = b2[o];

  float y_reg = 0.0f;
  if (tid < 128) {
    y_reg = y0[b * N_STATE + tid];
    out[(size_t)b * N_K_STEPS * N_STATE + tid] = y_reg;   // row 0 = y0
  }
  if (tid == 0) {
    float* zf = (float*)S.zs4;
    zf[161] = 0.0f; zf[162] = 0.0f; zf[163] = 0.0f;       // pad
  }
  __syncthreads();

  float* zsf = (float*)S.zs4;
  const float4* hs4 = (const float4*)S.hs;

  for (int s = 0; s < n_steps - 1; ++s) {
    const float t0 = S.tsh[s];
    const float hstep = S.tsh[s + 1] - t0;

    // ---- step setup: Hermite-interpolated u for stages 1..5
    // (first read of ustg is 2 barriers later; no extra sync needed)
    if (tid < 160) {
      int stg = (tid >> 5) + 1;        // 1..5
      int m   = tid & 31;
      float u0v = usb[s * N_INPUT + m];
      float u1v = usb[(s + 1) * N_INPUT + m];
      float hd1 = u1v - u0v;           // h*d[s+1] == u1-u0 exactly
      float hd0;
      if (s == 0) {
        hd0 = hd1;
      } else {
        float um  = usb[(s - 1) * N_INPUT + m];
        float dtp = t0 - S.tsh[s - 1];
        hd0 = hstep * (u0v - um) / dtp;
      }
      float th = c_C[stg];
      float t2 = th * th, t3 = t2 * th;
      S.ustg[stg][m] = (2.f*t3 - 3.f*t2 + 1.f) * u0v + (t3 - 2.f*t2 + th) * hd0
                     + (-2.f*t3 + 3.f*t2) * u1v + (t3 - t2) * hd1;
    }

    #pragma unroll 1
    for (int st = 0; st < 6; ++st) {
      // ---- (A) assemble z = [t, ytmp, u(theta)]; fold k_{st-1} from partials
      if (st == 0) {
        if (tid < 128)       zsf[1 + tid] = y_reg;
        else if (tid < 160)  zsf[129 + (tid - 128)] = usb[s * N_INPUT + (tid - 128)];
        else if (tid == 160) zsf[0] = t0;
      } else {
        if (tid < 128) {
          float kprev = S.partial[tid] + S.partial[128 + tid] + b2t;
          S.ksh[st - 1][tid] = kprev;
          float acc = c_A[st - 1][st - 1] * kprev;
          for (int j = 0; j < st - 1; ++j)
            acc += c_A[st - 1][j] * S.ksh[j][tid];
          zsf[1 + tid] = y_reg + hstep * acc;
        } else if (tid < 160) {
          zsf[129 + (tid - 128)] = S.ustg[st][tid - 128];
        } else if (tid == 160) {
          zsf[0] = t0 + c_C[st] * hstep;
        }
      }
      __syncthreads();

      // ---- (B) hidden layer: h[tid] = tanh(W1[tid,:] . z + b1[tid])
      //      41 float4 broadcasts; 4 independent FFMA2 chains
      {
        float2 a0 = make_float2(0.f, 0.f), a1 = a0, a2 = a0, a3 = a0;
        #pragma unroll
        for (int p = 0; p < 40; p += 2) {
          float4 zv = S.zs4[p];
          float4 wv = w1r[p];
          a0 = ffma2f(make_float2(wv.x, wv.y), make_float2(zv.x, zv.y), a0);
          a1 = ffma2f(make_float2(wv.z, wv.w), make_float2(zv.z, zv.w), a1);
          float4 zw = S.zs4[p + 1];
          float4 ww = w1r[p + 1];
          a2 = ffma2f(make_float2(ww.x, ww.y), make_float2(zw.x, zw.y), a2);
          a3 = ffma2f(make_float2(ww.z, ww.w), make_float2(zw.z, zw.w), a3);
        }
        {
          float4 zv = S.zs4[40];
          a0 = ffma2f(make_float2(w1r[40].x, w1r[40].y), make_float2(zv.x, zv.y), a0);
        }
        float sum = ((a0.x + a0.y) + (a1.x + a1.y))
                  + ((a2.x + a2.y) + (a3.x + a3.y)) + b1t;
        S.hs[tid] = fast_tanh(sum);
      }
      __syncthreads();

      // ---- (C) output layer: 2 threads per output, 32 k-quads each,
      //      float4 w2 loads (conflict-free) + float4 h broadcasts, 4 chains
      {
        float2 c0 = make_float2(0.f, 0.f), c1 = c0, c2 = c0, c3 = c0;
        #pragma unroll
        for (int j = 0; j < 32; j += 2) {
          float4 hv = hs4[qb + j];
          float4 wv = S.w2q[(qb + j) * 128 + o];
          c0 = ffma2f(make_float2(wv.x, wv.y), make_float2(hv.x, hv.y), c0);
          c1 = ffma2f(make_float2(wv.z, wv.w), make_float2(hv.z, hv.w), c1);
          float4 hw = hs4[qb + j + 1];
          float4 ww = S.w2q[(qb + j + 1) * 128 + o];
          c2 = ffma2f(make_float2(ww.x, ww.y), make_float2(hw.x, hw.y), c2);
          c3 = ffma2f(make_float2(ww.z, ww.w), make_float2(hw.z, hw.w), c3);
        }
        S.partial[half * 128 + o] = ((c0.x + c0.y) + (c1.x + c1.y))
                                  + ((c2.x + c2.y) + (c3.x + c3.y));
      }
      __syncthreads();
    }

    // ---- final Runge-Kutta combine + output write
    if (tid < 128) {
      float k5 = S.partial[tid] + S.partial[128 + tid] + b2t;
      float acc = c_B[5] * k5;
      #pragma unroll
      for (int j = 0; j < 5; ++j)
        acc += c_B[j] * S.ksh[j][tid];
      y_reg += hstep * acc;
      out[((size_t)b * N_K_STEPS + (s + 1)) * N_STATE + tid] = y_reg;
    }
    // next iteration's (A)-barrier provides ordering
  }
}

extern "C" void kernel_launch(void* const* d_in, const int* in_sizes, int n_in,
                              void* d_out, int out_size) {
  const float* ts = (const float*)d_in[0];
  const float* y0 = (const float*)d_in[1];
  const float* us = (const float*)d_in[2];
  const float* W1 = (const float*)d_in[3];
  const float* b1 = (const float*)d_in[4];
  const float* W2 = (const float*)d_in[5];
  const float* b2 = (const float*)d_in[6];
  float* out = (float*)d_out;

  const int n_steps = in_sizes[0];             // 512
  const int batch   = in_sizes[1] / N_STATE;   // 64

  const size_t smem_bytes = sizeof(SmemLayout);
  cudaFuncSetAttribute(ode_tsit5_kernel,
                       cudaFuncAttributeMaxDynamicSharedMemorySize, (int)smem_bytes);
  ode_tsit5_kernel<<<batch, 256, smem_bytes>>>(ts, y0, us, W1, b1, W2, b2, out, n_steps);
}